// round 8
// baseline (speedup 1.0000x reference)
#include <cuda_runtime.h>
#include <cuda_bf16.h>
#include <cstdint>

// Problem constants (fixed by the dataset)
#define NV 1024
#define NE 2048
#define FV 128
#define FE 64
#define HH 128
#define CC 16
#define BMAX 16

// ---------------- scratch (static __device__ arrays; no allocation) ----------
__device__ float g_A[(size_t)BMAX * NE * NE];    // 256 MB: multiplier*adj scratch
__device__ float g_Tt[(size_t)BMAX * NV * NE];   // 128 MB: T transposed per batch
__device__ float g_Y[(size_t)BMAX * NE * FE];
__device__ float g_X1[(size_t)BMAX * NV * HH];
__device__ float g_Z2[(size_t)BMAX * NE * FE];
__device__ float g_d[BMAX * NE];
__device__ float g_rc[BMAX * NE];
__device__ float g_cm[BMAX * NE];

// ======================= helpers ============================================
__device__ __forceinline__ uint32_t cvta_s(const void* p) {
    uint32_t a;
    asm("{ .reg .u64 t; cvta.to.shared.u64 t, %1; cvt.u32.u64 %0, t; }" : "=r"(a) : "l"(p));
    return a;
}

__device__ __forceinline__ uint32_t pack2(__nv_bfloat16 a, __nv_bfloat16 b) {
    return (uint32_t)__bfloat16_as_ushort(a) | ((uint32_t)__bfloat16_as_ushort(b) << 16);
}

// split float4 -> hi/lo bf16x4, store 8B to each of two smem tiles (prop kernel)
__device__ __forceinline__ void split_store(uint32_t hi_addr, uint32_t lo_addr, float4 v) {
    __nv_bfloat16 h0 = __float2bfloat16_rn(v.x);
    __nv_bfloat16 h1 = __float2bfloat16_rn(v.y);
    __nv_bfloat16 h2 = __float2bfloat16_rn(v.z);
    __nv_bfloat16 h3 = __float2bfloat16_rn(v.w);
    __nv_bfloat16 l0 = __float2bfloat16_rn(v.x - __bfloat162float(h0));
    __nv_bfloat16 l1 = __float2bfloat16_rn(v.y - __bfloat162float(h1));
    __nv_bfloat16 l2 = __float2bfloat16_rn(v.z - __bfloat162float(h2));
    __nv_bfloat16 l3 = __float2bfloat16_rn(v.w - __bfloat162float(h3));
    asm volatile("st.shared.v2.u32 [%0], {%1,%2};" :: "r"(hi_addr),
                 "r"(pack2(h0, h1)), "r"(pack2(h2, h3)) : "memory");
    asm volatile("st.shared.v2.u32 [%0], {%1,%2};" :: "r"(lo_addr),
                 "r"(pack2(l0, l1)), "r"(pack2(l2, l3)) : "memory");
}

// split two float4 (8 consecutive k) -> one 16B hi v4 store + one 16B lo v4 store
__device__ __forceinline__ void split_store8(uint32_t hi_addr, float4 a, float4 b) {
    __nv_bfloat16 h0 = __float2bfloat16_rn(a.x);
    __nv_bfloat16 h1 = __float2bfloat16_rn(a.y);
    __nv_bfloat16 h2 = __float2bfloat16_rn(a.z);
    __nv_bfloat16 h3 = __float2bfloat16_rn(a.w);
    __nv_bfloat16 h4 = __float2bfloat16_rn(b.x);
    __nv_bfloat16 h5 = __float2bfloat16_rn(b.y);
    __nv_bfloat16 h6 = __float2bfloat16_rn(b.z);
    __nv_bfloat16 h7 = __float2bfloat16_rn(b.w);
    __nv_bfloat16 l0 = __float2bfloat16_rn(a.x - __bfloat162float(h0));
    __nv_bfloat16 l1 = __float2bfloat16_rn(a.y - __bfloat162float(h1));
    __nv_bfloat16 l2 = __float2bfloat16_rn(a.z - __bfloat162float(h2));
    __nv_bfloat16 l3 = __float2bfloat16_rn(a.w - __bfloat162float(h3));
    __nv_bfloat16 l4 = __float2bfloat16_rn(b.x - __bfloat162float(h4));
    __nv_bfloat16 l5 = __float2bfloat16_rn(b.y - __bfloat162float(h5));
    __nv_bfloat16 l6 = __float2bfloat16_rn(b.z - __bfloat162float(h6));
    __nv_bfloat16 l7 = __float2bfloat16_rn(b.w - __bfloat162float(h7));
    asm volatile("st.shared.v4.u32 [%0], {%1,%2,%3,%4};" :: "r"(hi_addr),
                 "r"(pack2(h0, h1)), "r"(pack2(h2, h3)),
                 "r"(pack2(h4, h5)), "r"(pack2(h6, h7)) : "memory");
    asm volatile("st.shared.v4.u32 [%0], {%1,%2,%3,%4};" :: "r"(hi_addr + 16),
                 "r"(pack2(l0, l1)), "r"(pack2(l2, l3)),
                 "r"(pack2(l4, l5)), "r"(pack2(l6, l7)) : "memory");
}

__device__ __forceinline__ void ldm_x4(uint32_t* r, uint32_t addr) {
    asm volatile("ldmatrix.sync.aligned.m8n8.x4.shared.b16 {%0,%1,%2,%3}, [%4];"
                 : "=r"(r[0]), "=r"(r[1]), "=r"(r[2]), "=r"(r[3]) : "r"(addr));
}
__device__ __forceinline__ void ldm_x2_t(uint32_t* r, uint32_t addr) {
    asm volatile("ldmatrix.sync.aligned.m8n8.x2.trans.shared.b16 {%0,%1}, [%2];"
                 : "=r"(r[0]), "=r"(r[1]) : "r"(addr));
}

__device__ __forceinline__ void mma_bf16(float* c, const uint32_t* a, const uint32_t* b) {
    asm volatile(
        "mma.sync.aligned.m16n8k16.row.col.f32.bf16.bf16.f32 "
        "{%0,%1,%2,%3}, {%4,%5,%6,%7}, {%8,%9}, {%0,%1,%2,%3};"
        : "+f"(c[0]), "+f"(c[1]), "+f"(c[2]), "+f"(c[3])
        : "r"(a[0]), "r"(a[1]), "r"(a[2]), "r"(a[3]), "r"(b[0]), "r"(b[1]));
}

// ============ tensor-core multiplier via mma.sync (symmetric) ================
// Interleaved hi|lo smem layout: per operand one tile, rows 128, stride 144B;
// 8-k group g at row*144 + g*32 (hi 16B, then lo 16B).
#define KC 32
#define MROW 144
#define MTILE 18432            // 128 * 144 (one operand pair: hi+lo interleaved)
#define STG 36864              // A-pair + B-pair per stage

__global__ void __launch_bounds__(512, 1) mult_mma_kernel(
    const float* __restrict__ src, const float* __restrict__ dvec,
    const float* __restrict__ adj, float* __restrict__ Aout,
    float* __restrict__ cm, int n, int K)
{
    extern __shared__ char smc[];
    const uint32_t sb = cvta_s(smc);
    const int tid = threadIdx.x;
    const int lane = tid & 31;
    const int wid = tid >> 5;
    const int wm = (wid >> 2) * 32;
    const int wn = (wid & 3) * 32;
    const int b = blockIdx.z;
    const float* Sb = src + (size_t)b * (size_t)(NV * NE);
    const float* db = dvec + (size_t)b * K;
    const float* adjb = adj + (size_t)b * n * n;
    float* Ab = Aout + (size_t)b * n * n;
    float* cmb = cm + (size_t)b * n;

    // decode lower-triangle pair index: by >= bx
    int idx = blockIdx.x;
    int by = (int)((sqrtf(8.0f * (float)idx + 1.0f) - 1.0f) * 0.5f);
    while ((by + 1) * (by + 2) / 2 <= idx) by++;
    while (by * (by + 1) / 2 > idx) by--;
    int bx = idx - by * (by + 1) / 2;
    const int m0 = by * 128, n0 = bx * 128;
    const bool diag_blk = (bx == by);

    float acc[2][4][4];
#pragma unroll
    for (int mi = 0; mi < 2; mi++)
#pragma unroll
        for (int ni = 0; ni < 4; ni++)
#pragma unroll
            for (int q = 0; q < 4; q++) acc[mi][ni][q] = 0.f;

    float4 ra0, ra1, rb0, rb1, rd0, rd1;
    const int ldrow = tid >> 2;        // 0..127
    const int ldg8 = tid & 3;          // 8-k group 0..3

#define LOAD_CHUNK(k0)                                                        \
    {                                                                         \
        const float* ap = Sb + (size_t)(m0 + ldrow) * K + (k0) + ldg8 * 8;    \
        ra0 = *(const float4*)(ap);                                           \
        ra1 = *(const float4*)(ap + 4);                                       \
        const float* bp = Sb + (size_t)(n0 + ldrow) * K + (k0) + ldg8 * 8;    \
        rb0 = *(const float4*)(bp);                                           \
        rb1 = *(const float4*)(bp + 4);                                       \
        rd0 = *(const float4*)(db + (k0) + ldg8 * 8);                         \
        rd1 = *(const float4*)(db + (k0) + ldg8 * 8 + 4);                     \
    }

#define STORE_CHUNK(s)                                                        \
    {                                                                         \
        uint32_t base = sb + (s) * STG + (uint32_t)(ldrow * MROW + ldg8 * 32); \
        split_store8(base, ra0, ra1);                                         \
        float4 v0 = rb0, v1 = rb1;                                            \
        v0.x *= rd0.x; v0.y *= rd0.y; v0.z *= rd0.z; v0.w *= rd0.w;           \
        v1.x *= rd1.x; v1.y *= rd1.y; v1.z *= rd1.z; v1.w *= rd1.w;           \
        split_store8(base + MTILE, v0, v1);                                   \
    }

    const int nk = K / KC;
    LOAD_CHUNK(0);
    STORE_CHUNK(0);
    __syncthreads();

    for (int i = 0; i < nk; i++) {
        if (i + 1 < nk) LOAD_CHUNK((i + 1) * KC);
        {
            uint32_t base = sb + (i & 1) * STG;
#pragma unroll
            for (int kk = 0; kk < 2; kk++) {
                const int kb = kk * 16;
                uint32_t ahi[2][4], alo[2][4], bhi[4][2], blo[4][2];
#pragma unroll
                for (int mi = 0; mi < 2; mi++) {
                    int row = wm + mi * 16 + (lane & 15);
                    uint32_t addr = base + row * MROW + kb * 4 + ((lane >> 4) << 5);
                    ldm_x4(ahi[mi], addr);
                    ldm_x4(alo[mi], addr + 16);
                }
#pragma unroll
                for (int np = 0; np < 2; np++) {
                    int row = wn + np * 16 + ((lane >> 4) << 3) + (lane & 7);
                    uint32_t addr = base + MTILE + row * MROW + kb * 4 + (((lane >> 3) & 1) << 5);
                    uint32_t t4[4];
                    ldm_x4(t4, addr);
                    bhi[2 * np][0] = t4[0]; bhi[2 * np][1] = t4[1];
                    bhi[2 * np + 1][0] = t4[2]; bhi[2 * np + 1][1] = t4[3];
                    ldm_x4(t4, addr + 16);
                    blo[2 * np][0] = t4[0]; blo[2 * np][1] = t4[1];
                    blo[2 * np + 1][0] = t4[2]; blo[2 * np + 1][1] = t4[3];
                }
#pragma unroll
                for (int mi = 0; mi < 2; mi++)
#pragma unroll
                    for (int ni = 0; ni < 4; ni++)
                        mma_bf16(acc[mi][ni], ahi[mi], bhi[ni]);
#pragma unroll
                for (int mi = 0; mi < 2; mi++)
#pragma unroll
                    for (int ni = 0; ni < 4; ni++)
                        mma_bf16(acc[mi][ni], alo[mi], bhi[ni]);
#pragma unroll
                for (int mi = 0; mi < 2; mi++)
#pragma unroll
                    for (int ni = 0; ni < 4; ni++)
                        mma_bf16(acc[mi][ni], ahi[mi], blo[ni]);
            }
        }
        if (i + 1 < nk) STORE_CHUNK((i + 1) & 1);
        __syncthreads();
    }

    // ---- epilogue pass 1: original tile (rows m0.., cols n0..) ----
    float cmax[4][2];
#pragma unroll
    for (int ni = 0; ni < 4; ni++) { cmax[ni][0] = 0.f; cmax[ni][1] = 0.f; }

#pragma unroll
    for (int mi = 0; mi < 2; mi++)
#pragma unroll
        for (int ni = 0; ni < 4; ni++) {
            int gm_base = m0 + wm + mi * 16 + (lane >> 2);
            int gn = n0 + wn + ni * 8 + (lane & 3) * 2;
#pragma unroll
            for (int h = 0; h < 2; h++) {
                int gm = gm_base + h * 8;
                float2 a2 = *(const float2*)(adjb + (size_t)gm * n + gn);
                float v0 = acc[mi][ni][h * 2 + 0];
                float v1 = acc[mi][ni][h * 2 + 1];
                if (gm == gn) v0 = 1.0f;
                if (gm == gn + 1) v1 = 1.0f;
                float o0 = v0 * a2.x, o1 = v1 * a2.y;
                *(float2*)(Ab + (size_t)gm * n + gn) = make_float2(o0, o1);
                cmax[ni][0] = fmaxf(cmax[ni][0], o0);
                cmax[ni][1] = fmaxf(cmax[ni][1], o1);
            }
        }
#pragma unroll
    for (int ni = 0; ni < 4; ni++)
#pragma unroll
        for (int c = 0; c < 2; c++) {
            float v = cmax[ni][c];
            v = fmaxf(v, __shfl_xor_sync(0xffffffffu, v, 4));
            v = fmaxf(v, __shfl_xor_sync(0xffffffffu, v, 8));
            v = fmaxf(v, __shfl_xor_sync(0xffffffffu, v, 16));
            if (lane < 4) {
                int gn = n0 + wn + ni * 8 + lane * 2 + c;
                atomicMax((int*)(cmb + gn), __float_as_int(v));
            }
        }

    // ---- epilogue pass 2: mirrored tile (rows n0.., cols m0..) ----
    if (!diag_blk) {
#pragma unroll
        for (int mi = 0; mi < 2; mi++)
#pragma unroll
            for (int h = 0; h < 2; h++) {
                int gm = m0 + wm + mi * 16 + (lane >> 2) + h * 8;  // mirror column
                float rmax = 0.f;
#pragma unroll
                for (int ni = 0; ni < 4; ni++) {
#pragma unroll
                    for (int c = 0; c < 2; c++) {
                        int gn = n0 + wn + ni * 8 + (lane & 3) * 2 + c;  // mirror row
                        float av = adjb[(size_t)gn * n + gm];
                        float o = acc[mi][ni][h * 2 + c] * av;
                        Ab[(size_t)gn * n + gm] = o;
                        rmax = fmaxf(rmax, o);
                    }
                }
                rmax = fmaxf(rmax, __shfl_xor_sync(0xffffffffu, rmax, 1));
                rmax = fmaxf(rmax, __shfl_xor_sync(0xffffffffu, rmax, 2));
                if ((lane & 3) == 0)
                    atomicMax((int*)(cmb + gm), __float_as_int(rmax));
            }
    }
}

// ============ propagation GEMM via mma.sync ==================================
// C(MxN) = A(MxK, fp32) @ (rc ⊙ Y)(KxN, fp32) + bias, optional relu.
#define PA_STRIDE 80
#define PA_TILE 10240          // 128*80
#define PB_STRIDE 144
#define PB_TILE 4608           // 32*144
#define PSTG (2*PA_TILE + 2*PB_TILE)   // 29696 per stage

__global__ void __launch_bounds__(256, 1) prop_mma_kernel(
    const float* __restrict__ A, const float* __restrict__ Y,
    const float* __restrict__ rc, const float* __restrict__ bias,
    float* __restrict__ C, int M, int N, int K, int relu)
{
    extern __shared__ char smc[];
    const uint32_t sb = cvta_s(smc);
    const int tid = threadIdx.x;
    const int lane = tid & 31;
    const int wid = tid >> 5;
    const int wm = (wid >> 1) * 32;
    const int wn = (wid & 1) * 32;
    const int b = blockIdx.z;
    const float* Ab = A + (size_t)b * M * K;
    const float* Yb = Y + (size_t)b * K * N;
    const float* rcb = rc + (size_t)b * K;
    float* Cb = C + (size_t)b * M * N;
    const int m0 = blockIdx.y * 128, n0 = blockIdx.x * 64;

    float acc[2][4][4];
#pragma unroll
    for (int mi = 0; mi < 2; mi++)
#pragma unroll
        for (int ni = 0; ni < 4; ni++)
#pragma unroll
            for (int q = 0; q < 4; q++) acc[mi][ni][q] = 0.f;

    float4 rA[4];
    float4 rB[2];
    float rS[2];

#define P_LOAD(k0)                                                            \
    {                                                                         \
        _Pragma("unroll")                                                     \
        for (int j = 0; j < 4; j++) {                                         \
            int idx2 = tid + 256 * j;                                         \
            int r = idx2 >> 3, c4 = idx2 & 7;                                 \
            rA[j] = *(const float4*)(Ab + (size_t)(m0 + r) * K + (k0) + c4 * 4); \
        }                                                                     \
        _Pragma("unroll")                                                     \
        for (int j = 0; j < 2; j++) {                                         \
            int idx2 = tid + 256 * j;                                         \
            int r = idx2 >> 4, c4 = idx2 & 15;                                \
            rB[j] = *(const float4*)(Yb + (size_t)((k0) + r) * N + n0 + c4 * 4); \
            rS[j] = rcb[(k0) + r];                                            \
        }                                                                     \
    }

#define P_STORE(s)                                                            \
    {                                                                         \
        uint32_t base = sb + (s) * PSTG;                                      \
        _Pragma("unroll")                                                     \
        for (int j = 0; j < 4; j++) {                                         \
            int idx2 = tid + 256 * j;                                         \
            int r = idx2 >> 3, c4 = idx2 & 7;                                 \
            uint32_t off = (uint32_t)(r * PA_STRIDE + c4 * 8);                \
            split_store(base + off, base + PA_TILE + off, rA[j]);             \
        }                                                                     \
        _Pragma("unroll")                                                     \
        for (int j = 0; j < 2; j++) {                                         \
            int idx2 = tid + 256 * j;                                         \
            int r = idx2 >> 4, c4 = idx2 & 15;                                \
            float4 v = rB[j];                                                 \
            v.x *= rS[j]; v.y *= rS[j]; v.z *= rS[j]; v.w *= rS[j];           \
            uint32_t off = (uint32_t)(r * PB_STRIDE + c4 * 8);                \
            split_store(base + 2 * PA_TILE + off, base + 2 * PA_TILE + PB_TILE + off, v); \
        }                                                                     \
    }

    const int nk = K / KC;
    P_LOAD(0);
    P_STORE(0);
    __syncthreads();

    for (int i = 0; i < nk; i++) {
        if (i + 1 < nk) P_LOAD((i + 1) * KC);
        {
            uint32_t base = sb + (i & 1) * PSTG;
            uint32_t bbase = base + 2 * PA_TILE;
#pragma unroll
            for (int kk = 0; kk < 2; kk++) {
                const int kb = kk * 16;
                uint32_t ahi[2][4], alo[2][4], bhi[4][2], blo[4][2];
#pragma unroll
                for (int mi = 0; mi < 2; mi++) {
                    int row = wm + mi * 16 + (lane & 15);
                    uint32_t addr = base + row * PA_STRIDE + (kb + ((lane >> 4) << 3)) * 2;
                    ldm_x4(ahi[mi], addr);
                    ldm_x4(alo[mi], addr + PA_TILE);
                }
#pragma unroll
                for (int ni = 0; ni < 4; ni++) {
                    int krow = kb + (lane & 7) + ((lane >> 3) & 1) * 8;
                    uint32_t addr = bbase + krow * PB_STRIDE + (wn + ni * 8) * 2;
                    ldm_x2_t(bhi[ni], addr);
                    ldm_x2_t(blo[ni], addr + PB_TILE);
                }
#pragma unroll
                for (int mi = 0; mi < 2; mi++)
#pragma unroll
                    for (int ni = 0; ni < 4; ni++)
                        mma_bf16(acc[mi][ni], ahi[mi], bhi[ni]);
#pragma unroll
                for (int mi = 0; mi < 2; mi++)
#pragma unroll
                    for (int ni = 0; ni < 4; ni++)
                        mma_bf16(acc[mi][ni], alo[mi], bhi[ni]);
#pragma unroll
                for (int mi = 0; mi < 2; mi++)
#pragma unroll
                    for (int ni = 0; ni < 4; ni++)
                        mma_bf16(acc[mi][ni], ahi[mi], blo[ni]);
            }
        }
        if (i + 1 < nk) P_STORE((i + 1) & 1);
        __syncthreads();
    }

#pragma unroll
    for (int mi = 0; mi < 2; mi++)
#pragma unroll
        for (int ni = 0; ni < 4; ni++) {
            int gm_base = m0 + wm + mi * 16 + (lane >> 2);
            int gn = n0 + wn + ni * 8 + (lane & 3) * 2;
            float bi0 = bias[gn], bi1 = bias[gn + 1];
#pragma unroll
            for (int h = 0; h < 2; h++) {
                int gm = gm_base + h * 8;
                float v0 = acc[mi][ni][h * 2 + 0] + bi0;
                float v1 = acc[mi][ni][h * 2 + 1] + bi1;
                if (relu) { v0 = fmaxf(v0, 0.f); v1 = fmaxf(v1, 0.f); }
                *(float2*)(Cb + (size_t)gm * N + gn) = make_float2(v0, v1);
            }
        }
}

// ---------------- transpose: Tt[b][e][v] = T[b][v][e] ------------------------
__global__ void transpose_kernel(const float* __restrict__ T, float* __restrict__ Tt) {
    __shared__ float tile[32][33];
    int b = blockIdx.z;
    const float* Tb = T + (size_t)b * NV * NE;
    float* Ob = Tt + (size_t)b * NV * NE;
    int e0 = blockIdx.x * 32, v0 = blockIdx.y * 32;
    int tx = threadIdx.x, ty = threadIdx.y;
#pragma unroll
    for (int j = 0; j < 32; j += 8)
        tile[ty + j][tx] = Tb[(size_t)(v0 + ty + j) * NE + e0 + tx];
    __syncthreads();
#pragma unroll
    for (int j = 0; j < 32; j += 8)
        Ob[(size_t)(e0 + ty + j) * NV + v0 + tx] = tile[tx][ty + j];
}

// ---------------- d = rows(X) . p  (warp per row) ----------------------------
__global__ void rowdot_kernel(const float* __restrict__ X, const float* __restrict__ p,
                              float* __restrict__ dout, int rows, int F) {
    int lane = threadIdx.x & 31;
    int wid  = threadIdx.x >> 5;
    int row  = blockIdx.x * 8 + wid;
    int b    = blockIdx.y;
    if (row >= rows) return;
    const float* xr = X + ((size_t)b * rows + row) * F;
    float s = 0.f;
    for (int f = lane; f < F; f += 32) s += xr[f] * p[f];
#pragma unroll
    for (int o = 16; o; o >>= 1) s += __shfl_xor_sync(0xffffffffu, s, o);
    if (lane == 0) dout[(size_t)b * rows + row] = s;
}

// ---------------- generic SIMT GEMM (small problems) -------------------------
__global__ void __launch_bounds__(256) gemm64_kernel(
    const float* __restrict__ A, const float* __restrict__ Bm, float* __restrict__ C,
    int M, int N, int K,
    long strideA, long strideB, long strideC,
    const float* __restrict__ rowScale, int strideRS,
    const float* __restrict__ bias, int reluOut, int reluA) {
    int b = blockIdx.z;
    const float* Ab = A + (size_t)b * strideA;
    const float* Bb = Bm + (size_t)b * strideB;
    float* Cb       = C + (size_t)b * strideC;
    const float* rs = rowScale ? rowScale + (size_t)b * strideRS : nullptr;
    int m0 = blockIdx.y * 64, n0 = blockIdx.x * 64;
    __shared__ float As[16][64];
    __shared__ float Bs[16][64];
    int tid = threadIdx.x;
    int tx = tid & 15, ty = tid >> 4;
    int arow = tid >> 2, ac4 = tid & 3;
    int bk = tid >> 4, bn4 = tid & 15;
    float acc[4][4] = {};
    for (int k0 = 0; k0 < K; k0 += 16) {
        float4 av = *(const float4*)(Ab + (size_t)(m0 + arow) * K + k0 + ac4 * 4);
        if (reluA) {
            av.x = fmaxf(av.x, 0.f); av.y = fmaxf(av.y, 0.f);
            av.z = fmaxf(av.z, 0.f); av.w = fmaxf(av.w, 0.f);
        }
        As[ac4 * 4 + 0][arow] = av.x; As[ac4 * 4 + 1][arow] = av.y;
        As[ac4 * 4 + 2][arow] = av.z; As[ac4 * 4 + 3][arow] = av.w;
        int col = n0 + bn4 * 4;
        float4 bv = make_float4(0.f, 0.f, 0.f, 0.f);
        if (col < N) bv = *(const float4*)(Bb + (size_t)(k0 + bk) * N + col);
        if (rs) { float s = rs[k0 + bk]; bv.x *= s; bv.y *= s; bv.z *= s; bv.w *= s; }
        *(float4*)&Bs[bk][bn4 * 4] = bv;
        __syncthreads();
#pragma unroll
        for (int k = 0; k < 16; k++) {
            float4 a  = *(const float4*)&As[k][ty * 4];
            float4 bq = *(const float4*)&Bs[k][tx * 4];
            acc[0][0] += a.x * bq.x; acc[0][1] += a.x * bq.y; acc[0][2] += a.x * bq.z; acc[0][3] += a.x * bq.w;
            acc[1][0] += a.y * bq.x; acc[1][1] += a.y * bq.y; acc[1][2] += a.y * bq.z; acc[1][3] += a.y * bq.w;
            acc[2][0] += a.z * bq.x; acc[2][1] += a.z * bq.y; acc[2][2] += a.z * bq.z; acc[2][3] += a.z * bq.w;
            acc[3][0] += a.w * bq.x; acc[3][1] += a.w * bq.y; acc[3][2] += a.w * bq.z; acc[3][3] += a.w * bq.w;
        }
        __syncthreads();
    }
#pragma unroll
    for (int i = 0; i < 4; i++) {
        int gm = m0 + ty * 4 + i;
#pragma unroll
        for (int j = 0; j < 4; j++) {
            int gn = n0 + tx * 4 + j;
            if (gn < N) {
                float v = acc[i][j];
                if (bias) v += bias[gn];
                if (reluOut) v = fmaxf(v, 0.f);
                Cb[(size_t)gm * N + gn] = v;
            }
        }
    }
}

__global__ void rcinv_kernel(const float* __restrict__ cm, float* __restrict__ rc, int n) {
    int i = blockIdx.x * blockDim.x + threadIdx.x;
    if (i < n) rc[i] = 1.0f / cm[i];
}

// ---------------- launch -----------------------------------------------------
extern "C" void kernel_launch(void* const* d_in, const int* in_sizes, int n_in,
                              void* d_out, int out_size) {
    const float* X     = (const float*)d_in[0];
    const float* Z     = (const float*)d_in[1];
    const float* adj_e = (const float*)d_in[2];
    const float* adj_v = (const float*)d_in[3];
    const float* Tm    = (const float*)d_in[4];
    const float* W1    = (const float*)d_in[5];
    const float* b1    = (const float*)d_in[6];
    const float* p1    = (const float*)d_in[7];
    const float* W2    = (const float*)d_in[8];
    const float* b2    = (const float*)d_in[9];
    const float* p2    = (const float*)d_in[10];
    const float* W3    = (const float*)d_in[11];
    const float* b3    = (const float*)d_in[12];
    const float* p3    = (const float*)d_in[13];
    float* out = (float*)d_out;

    int Bn = in_sizes[0] / (NV * FV);

    cudaFuncSetAttribute(mult_mma_kernel,
                         cudaFuncAttributeMaxDynamicSharedMemorySize, 2 * STG);
    cudaFuncSetAttribute(prop_mma_kernel,
                         cudaFuncAttributeMaxDynamicSharedMemorySize, 2 * PSTG);
    const int MULT_SMEM = 2 * STG;
    const int PROP_SMEM = 2 * PSTG;

    float *A, *Tt, *Y, *X1, *Z2, *dv, *rc, *cm;
    cudaGetSymbolAddress((void**)&A,  g_A);
    cudaGetSymbolAddress((void**)&Tt, g_Tt);
    cudaGetSymbolAddress((void**)&Y,  g_Y);
    cudaGetSymbolAddress((void**)&X1, g_X1);
    cudaGetSymbolAddress((void**)&Z2, g_Z2);
    cudaGetSymbolAddress((void**)&dv, g_d);
    cudaGetSymbolAddress((void**)&rc, g_rc);
    cudaGetSymbolAddress((void**)&cm, g_cm);

    const int NPAIR_V = (NV / 128) * (NV / 128 + 1) / 2;   // 36
    const int NPAIR_E = (NE / 128) * (NE / 128 + 1) / 2;   // 136

    // transpose T once (for the edge layer)
    transpose_kernel<<<dim3(NE / 32, NV / 32, Bn), dim3(32, 8)>>>(Tm, Tt);

    // ===== Layer 1 (node): X1 = relu(norm(M1*adj_v) @ (X@W1) + b1) =====
    rowdot_kernel<<<dim3(NE / 8, Bn), 256>>>(Z, p1, dv, NE, FE);
    gemm64_kernel<<<dim3(HH / 64, NV / 64, Bn), 256>>>(
        X, W1, Y, NV, HH, FV, (long)NV * FV, 0, (long)NV * HH, nullptr, 0, nullptr, 0, 0);
    cudaMemsetAsync(cm, 0, (size_t)Bn * NV * 4);
    mult_mma_kernel<<<dim3(NPAIR_V, 1, Bn), 512, MULT_SMEM>>>(Tm, dv, adj_v, A, cm, NV, NE);
    rcinv_kernel<<<(Bn * NV + 255) / 256, 256>>>(cm, rc, Bn * NV);
    prop_mma_kernel<<<dim3(HH / 64, NV / 128, Bn), 256, PROP_SMEM>>>(
        A, Y, rc, b1, X1, NV, HH, NV, 1);

    // ===== Layer 2 (edge): Z2 = relu(norm(M2*adj_e) @ (relu(Z)@W2) + b2) =====
    rowdot_kernel<<<dim3(NV / 8, Bn), 256>>>(X1, p2, dv, NV, HH);
    gemm64_kernel<<<dim3(1, NE / 64, Bn), 256>>>(
        Z, W2, Y, NE, FE, FE, (long)NE * FE, 0, (long)NE * FE, nullptr, 0, nullptr, 0, 1);
    cudaMemsetAsync(cm, 0, (size_t)Bn * NE * 4);
    mult_mma_kernel<<<dim3(NPAIR_E, 1, Bn), 512, MULT_SMEM>>>(Tt, dv, adj_e, A, cm, NE, NV);
    rcinv_kernel<<<(Bn * NE + 255) / 256, 256>>>(cm, rc, Bn * NE);
    prop_mma_kernel<<<dim3(FE / 64, NE / 128, Bn), 256, PROP_SMEM>>>(
        A, Y, rc, b2, Z2, NE, FE, NE, 1);

    // ===== Layer 3 (node): out = norm(M3*adj_v) @ (X1@W3) + b3 =====
    rowdot_kernel<<<dim3(NE / 8, Bn), 256>>>(Z2, p3, dv, NE, FE);
    gemm64_kernel<<<dim3(1, NV / 64, Bn), 256>>>(
        X1, W3, Y, NV, CC, HH, (long)NV * HH, 0, (long)NV * CC, nullptr, 0, nullptr, 0, 0);
    cudaMemsetAsync(cm, 0, (size_t)Bn * NV * 4);
    mult_mma_kernel<<<dim3(NPAIR_V, 1, Bn), 512, MULT_SMEM>>>(Tm, dv, adj_v, A, cm, NV, NE);
    rcinv_kernel<<<(Bn * NV + 255) / 256, 256>>>(cm, rc, Bn * NV);
    gemm64_kernel<<<dim3(1, NV / 64, Bn), 256>>>(
        A, Y, out, NV, CC, NV, (long)NV * NV, (long)NV * CC, (long)NV * CC, rc, NV, b3, 0, 0);
}

// round 9
// speedup vs baseline: 1.0531x; 1.0531x over previous
#include <cuda_runtime.h>
#include <cuda_bf16.h>
#include <cstdint>

// Problem constants (fixed by the dataset)
#define NV 1024
#define NE 2048
#define FV 128
#define FE 64
#define HH 128
#define CC 16
#define BMAX 16

// ---------------- scratch (static __device__ arrays; no allocation) ----------
__device__ float g_A[(size_t)BMAX * NE * NE];    // 256 MB
__device__ float g_Tt[(size_t)BMAX * NV * NE];   // 128 MB
__device__ uint4 g_SpT [(size_t)BMAX * NV * (NE / 8) * 2];   // 128 MB: split(T)
__device__ uint4 g_SpTt[(size_t)BMAX * NE * (NV / 8) * 2];   // 128 MB: split(Tt)
__device__ uint4 g_Dp  [(size_t)BMAX * NV * (NE / 8) * 2];   // 128 MB: split(src*d), reused
__device__ float g_Y[(size_t)BMAX * NE * FE];
__device__ float g_X1[(size_t)BMAX * NV * HH];
__device__ float g_Z2[(size_t)BMAX * NE * FE];
__device__ float g_d[BMAX * NE];
__device__ float g_rc[BMAX * NE];
__device__ float g_cm[BMAX * NE];

// ======================= helpers ============================================
__device__ __forceinline__ uint32_t cvta_s(const void* p) {
    uint32_t a;
    asm("{ .reg .u64 t; cvta.to.shared.u64 t, %1; cvt.u32.u64 %0, t; }" : "=r"(a) : "l"(p));
    return a;
}

__device__ __forceinline__ uint32_t pack2(__nv_bfloat16 a, __nv_bfloat16 b) {
    return (uint32_t)__bfloat16_as_ushort(a) | ((uint32_t)__bfloat16_as_ushort(b) << 16);
}

// split 8 consecutive fp32 -> 16B hi vec + 16B lo vec
__device__ __forceinline__ void split8g(float4 a, float4 b, uint4& hi, uint4& lo) {
    __nv_bfloat16 h0 = __float2bfloat16_rn(a.x);
    __nv_bfloat16 h1 = __float2bfloat16_rn(a.y);
    __nv_bfloat16 h2 = __float2bfloat16_rn(a.z);
    __nv_bfloat16 h3 = __float2bfloat16_rn(a.w);
    __nv_bfloat16 h4 = __float2bfloat16_rn(b.x);
    __nv_bfloat16 h5 = __float2bfloat16_rn(b.y);
    __nv_bfloat16 h6 = __float2bfloat16_rn(b.z);
    __nv_bfloat16 h7 = __float2bfloat16_rn(b.w);
    __nv_bfloat16 l0 = __float2bfloat16_rn(a.x - __bfloat162float(h0));
    __nv_bfloat16 l1 = __float2bfloat16_rn(a.y - __bfloat162float(h1));
    __nv_bfloat16 l2 = __float2bfloat16_rn(a.z - __bfloat162float(h2));
    __nv_bfloat16 l3 = __float2bfloat16_rn(a.w - __bfloat162float(h3));
    __nv_bfloat16 l4 = __float2bfloat16_rn(b.x - __bfloat162float(h4));
    __nv_bfloat16 l5 = __float2bfloat16_rn(b.y - __bfloat162float(h5));
    __nv_bfloat16 l6 = __float2bfloat16_rn(b.z - __bfloat162float(h6));
    __nv_bfloat16 l7 = __float2bfloat16_rn(b.w - __bfloat162float(h7));
    hi = make_uint4(pack2(h0, h1), pack2(h2, h3), pack2(h4, h5), pack2(h6, h7));
    lo = make_uint4(pack2(l0, l1), pack2(l2, l3), pack2(l4, l5), pack2(l6, l7));
}

// split float4 -> hi/lo bf16x4, store 8B to each of two smem tiles (prop kernel)
__device__ __forceinline__ void split_store(uint32_t hi_addr, uint32_t lo_addr, float4 v) {
    __nv_bfloat16 h0 = __float2bfloat16_rn(v.x);
    __nv_bfloat16 h1 = __float2bfloat16_rn(v.y);
    __nv_bfloat16 h2 = __float2bfloat16_rn(v.z);
    __nv_bfloat16 h3 = __float2bfloat16_rn(v.w);
    __nv_bfloat16 l0 = __float2bfloat16_rn(v.x - __bfloat162float(h0));
    __nv_bfloat16 l1 = __float2bfloat16_rn(v.y - __bfloat162float(h1));
    __nv_bfloat16 l2 = __float2bfloat16_rn(v.z - __bfloat162float(h2));
    __nv_bfloat16 l3 = __float2bfloat16_rn(v.w - __bfloat162float(h3));
    asm volatile("st.shared.v2.u32 [%0], {%1,%2};" :: "r"(hi_addr),
                 "r"(pack2(h0, h1)), "r"(pack2(h2, h3)) : "memory");
    asm volatile("st.shared.v2.u32 [%0], {%1,%2};" :: "r"(lo_addr),
                 "r"(pack2(l0, l1)), "r"(pack2(l2, l3)) : "memory");
}

__device__ __forceinline__ void ldm_x4(uint32_t* r, uint32_t addr) {
    asm volatile("ldmatrix.sync.aligned.m8n8.x4.shared.b16 {%0,%1,%2,%3}, [%4];"
                 : "=r"(r[0]), "=r"(r[1]), "=r"(r[2]), "=r"(r[3]) : "r"(addr));
}
__device__ __forceinline__ void ldm_x2_t(uint32_t* r, uint32_t addr) {
    asm volatile("ldmatrix.sync.aligned.m8n8.x2.trans.shared.b16 {%0,%1}, [%2];"
                 : "=r"(r[0]), "=r"(r[1]) : "r"(addr));
}

__device__ __forceinline__ void mma_bf16(float* c, const uint32_t* a, const uint32_t* b) {
    asm volatile(
        "mma.sync.aligned.m16n8k16.row.col.f32.bf16.bf16.f32 "
        "{%0,%1,%2,%3}, {%4,%5,%6,%7}, {%8,%9}, {%0,%1,%2,%3};"
        : "+f"(c[0]), "+f"(c[1]), "+f"(c[2]), "+f"(c[3])
        : "r"(a[0]), "r"(a[1]), "r"(a[2]), "r"(a[3]), "r"(b[0]), "r"(b[1]));
}

// ============ prep: split src (and src*d) into packed bf16 hi|lo groups ======
// Packed layout: per batch, group index g = row*(K/8)+kg -> two uint4 (hi16B, lo16B).
__global__ void prep_split_kernel(const float* __restrict__ src, const float* __restrict__ dvec,
                                  uint4* __restrict__ Sp, uint4* __restrict__ Dp,
                                  int rows, int K) {
    int b = blockIdx.z;
    size_t nG = (size_t)rows * (K >> 3);
    size_t g = (size_t)blockIdx.x * 256 + threadIdx.x;
    if (g >= nG) return;
    const float* s = src + (size_t)b * rows * K + g * 8;
    float4 a0 = *(const float4*)s;
    float4 a1 = *(const float4*)(s + 4);
    size_t o = ((size_t)b * nG + g) * 2;
    if (Sp) {
        uint4 hi, lo;
        split8g(a0, a1, hi, lo);
        Sp[o] = hi; Sp[o + 1] = lo;
    }
    if (Dp) {
        int kg = (int)(g % (size_t)(K >> 3));
        const float* dp = dvec + (size_t)b * K + kg * 8;
        float4 d0 = *(const float4*)dp;
        float4 d1 = *(const float4*)(dp + 4);
        a0.x *= d0.x; a0.y *= d0.y; a0.z *= d0.z; a0.w *= d0.w;
        a1.x *= d1.x; a1.y *= d1.y; a1.z *= d1.z; a1.w *= d1.w;
        uint4 hi, lo;
        split8g(a0, a1, hi, lo);
        Dp[o] = hi; Dp[o + 1] = lo;
    }
}

// ============ tensor-core multiplier: cp.async-fed, 4-stage, symmetric =======
#define KC 32
#define MROW 144
#define MTILE 18432            // 128 * 144 (one operand pair: hi+lo interleaved)
#define STG 36864              // A-pair + B-pair per stage
#define NSTAGE 4

#define CP16(d_, s_) asm volatile("cp.async.cg.shared.global [%0], [%1], 16;" \
    :: "r"(d_), "l"(__cvta_generic_to_global(s_)) : "memory")

__global__ void __launch_bounds__(512, 1) mult_mma_kernel(
    const uint4* __restrict__ Sp, const uint4* __restrict__ Dp,
    const float* __restrict__ adj, float* __restrict__ Aout,
    float* __restrict__ cm, int n, int K)
{
    extern __shared__ char smc[];
    const uint32_t sb = cvta_s(smc);
    const int tid = threadIdx.x;
    const int lane = tid & 31;
    const int wid = tid >> 5;
    const int wm = (wid >> 2) * 32;
    const int wn = (wid & 3) * 32;
    const int b = blockIdx.z;
    const float* adjb = adj + (size_t)b * n * n;
    float* Ab = Aout + (size_t)b * n * n;
    float* cmb = cm + (size_t)b * n;

    // decode lower-triangle pair index: by >= bx
    int idx = blockIdx.x;
    int by = (int)((sqrtf(8.0f * (float)idx + 1.0f) - 1.0f) * 0.5f);
    while ((by + 1) * (by + 2) / 2 <= idx) by++;
    while (by * (by + 1) / 2 > idx) by--;
    int bx = idx - by * (by + 1) / 2;
    const int m0 = by * 128, n0 = bx * 128;
    const bool diag_blk = (bx == by);

    float acc[2][4][4];
#pragma unroll
    for (int mi = 0; mi < 2; mi++)
#pragma unroll
        for (int ni = 0; ni < 4; ni++)
#pragma unroll
            for (int q = 0; q < 4; q++) acc[mi][ni][q] = 0.f;

    const int ldrow = tid >> 2;   // 0..127
    const int ldg8 = tid & 3;     // 0..3
    const int gpr = K >> 3;       // groups per row
    const size_t baseS = ((size_t)b * n + m0 + ldrow) * (size_t)gpr;
    const size_t baseD = ((size_t)b * n + n0 + ldrow) * (size_t)gpr;
    const uint32_t dstA = sb + (uint32_t)(ldrow * MROW + ldg8 * 32);

#define ISSUE(i)                                                              \
    {                                                                         \
        uint32_t da = dstA + ((i) & 3) * STG;                                 \
        const uint4* pa = Sp + (baseS + (size_t)((i) * 4 + ldg8)) * 2;        \
        CP16(da, pa); CP16(da + 16, pa + 1);                                  \
        const uint4* pb = Dp + (baseD + (size_t)((i) * 4 + ldg8)) * 2;        \
        CP16(da + MTILE, pb); CP16(da + MTILE + 16, pb + 1);                  \
        asm volatile("cp.async.commit_group;" ::: "memory");                  \
    }

    const int nk = K / KC;
    ISSUE(0); ISSUE(1); ISSUE(2);

    for (int i = 0; i < nk; i++) {
        asm volatile("cp.async.wait_group 2;" ::: "memory");
        __syncthreads();
        if (i + 3 < nk) {
            ISSUE(i + 3);
        } else {
            asm volatile("cp.async.commit_group;" ::: "memory");
        }
        uint32_t base = sb + (i & 3) * STG;
#pragma unroll
        for (int kk = 0; kk < 2; kk++) {
            const int kb = kk * 16;
            uint32_t ahi[2][4], alo[2][4], bhi[4][2], blo[4][2];
#pragma unroll
            for (int mi = 0; mi < 2; mi++) {
                int row = wm + mi * 16 + (lane & 15);
                uint32_t addr = base + row * MROW + kb * 4 + ((lane >> 4) << 5);
                ldm_x4(ahi[mi], addr);
                ldm_x4(alo[mi], addr + 16);
            }
#pragma unroll
            for (int np = 0; np < 2; np++) {
                int row = wn + np * 16 + ((lane >> 4) << 3) + (lane & 7);
                uint32_t addr = base + MTILE + row * MROW + kb * 4 + (((lane >> 3) & 1) << 5);
                uint32_t t4[4];
                ldm_x4(t4, addr);
                bhi[2 * np][0] = t4[0]; bhi[2 * np][1] = t4[1];
                bhi[2 * np + 1][0] = t4[2]; bhi[2 * np + 1][1] = t4[3];
                ldm_x4(t4, addr + 16);
                blo[2 * np][0] = t4[0]; blo[2 * np][1] = t4[1];
                blo[2 * np + 1][0] = t4[2]; blo[2 * np + 1][1] = t4[3];
            }
#pragma unroll
            for (int mi = 0; mi < 2; mi++)
#pragma unroll
                for (int ni = 0; ni < 4; ni++)
                    mma_bf16(acc[mi][ni], ahi[mi], bhi[ni]);
#pragma unroll
            for (int mi = 0; mi < 2; mi++)
#pragma unroll
                for (int ni = 0; ni < 4; ni++)
                    mma_bf16(acc[mi][ni], alo[mi], bhi[ni]);
#pragma unroll
            for (int mi = 0; mi < 2; mi++)
#pragma unroll
                for (int ni = 0; ni < 4; ni++)
                    mma_bf16(acc[mi][ni], ahi[mi], blo[ni]);
        }
    }

    // ---- epilogue pass 1: original tile (rows m0.., cols n0..) ----
    float cmax[4][2];
#pragma unroll
    for (int ni = 0; ni < 4; ni++) { cmax[ni][0] = 0.f; cmax[ni][1] = 0.f; }

#pragma unroll
    for (int mi = 0; mi < 2; mi++)
#pragma unroll
        for (int ni = 0; ni < 4; ni++) {
            int gm_base = m0 + wm + mi * 16 + (lane >> 2);
            int gn = n0 + wn + ni * 8 + (lane & 3) * 2;
#pragma unroll
            for (int h = 0; h < 2; h++) {
                int gm = gm_base + h * 8;
                float2 a2 = *(const float2*)(adjb + (size_t)gm * n + gn);
                float v0 = acc[mi][ni][h * 2 + 0];
                float v1 = acc[mi][ni][h * 2 + 1];
                if (gm == gn) v0 = 1.0f;
                if (gm == gn + 1) v1 = 1.0f;
                float o0 = v0 * a2.x, o1 = v1 * a2.y;
                *(float2*)(Ab + (size_t)gm * n + gn) = make_float2(o0, o1);
                cmax[ni][0] = fmaxf(cmax[ni][0], o0);
                cmax[ni][1] = fmaxf(cmax[ni][1], o1);
            }
        }
#pragma unroll
    for (int ni = 0; ni < 4; ni++)
#pragma unroll
        for (int c = 0; c < 2; c++) {
            float v = cmax[ni][c];
            v = fmaxf(v, __shfl_xor_sync(0xffffffffu, v, 4));
            v = fmaxf(v, __shfl_xor_sync(0xffffffffu, v, 8));
            v = fmaxf(v, __shfl_xor_sync(0xffffffffu, v, 16));
            if (lane < 4) {
                int gn = n0 + wn + ni * 8 + lane * 2 + c;
                atomicMax((int*)(cmb + gn), __float_as_int(v));
            }
        }

    // ---- epilogue pass 2: mirrored tile (rows n0.., cols m0..) ----
    if (!diag_blk) {
#pragma unroll
        for (int mi = 0; mi < 2; mi++)
#pragma unroll
            for (int h = 0; h < 2; h++) {
                int gm = m0 + wm + mi * 16 + (lane >> 2) + h * 8;  // mirror column
                float rmax = 0.f;
#pragma unroll
                for (int ni = 0; ni < 4; ni++) {
#pragma unroll
                    for (int c = 0; c < 2; c++) {
                        int gn = n0 + wn + ni * 8 + (lane & 3) * 2 + c;  // mirror row
                        float av = adjb[(size_t)gn * n + gm];
                        float o = acc[mi][ni][h * 2 + c] * av;
                        Ab[(size_t)gn * n + gm] = o;
                        rmax = fmaxf(rmax, o);
                    }
                }
                rmax = fmaxf(rmax, __shfl_xor_sync(0xffffffffu, rmax, 1));
                rmax = fmaxf(rmax, __shfl_xor_sync(0xffffffffu, rmax, 2));
                if ((lane & 3) == 0)
                    atomicMax((int*)(cmb + gm), __float_as_int(rmax));
            }
    }
}

// ============ propagation GEMM via mma.sync (unchanged, passing) =============
#define PA_STRIDE 80
#define PA_TILE 10240
#define PB_STRIDE 144
#define PB_TILE 4608
#define PSTG (2*PA_TILE + 2*PB_TILE)

__global__ void __launch_bounds__(256, 1) prop_mma_kernel(
    const float* __restrict__ A, const float* __restrict__ Y,
    const float* __restrict__ rc, const float* __restrict__ bias,
    float* __restrict__ C, int M, int N, int K, int relu)
{
    extern __shared__ char smc[];
    const uint32_t sb = cvta_s(smc);
    const int tid = threadIdx.x;
    const int lane = tid & 31;
    const int wid = tid >> 5;
    const int wm = (wid >> 1) * 32;
    const int wn = (wid & 1) * 32;
    const int b = blockIdx.z;
    const float* Ab = A + (size_t)b * M * K;
    const float* Yb = Y + (size_t)b * K * N;
    const float* rcb = rc + (size_t)b * K;
    float* Cb = C + (size_t)b * M * N;
    const int m0 = blockIdx.y * 128, n0 = blockIdx.x * 64;

    float acc[2][4][4];
#pragma unroll
    for (int mi = 0; mi < 2; mi++)
#pragma unroll
        for (int ni = 0; ni < 4; ni++)
#pragma unroll
            for (int q = 0; q < 4; q++) acc[mi][ni][q] = 0.f;

    float4 rA[4];
    float4 rB[2];
    float rS[2];

#define P_LOAD(k0)                                                            \
    {                                                                         \
        _Pragma("unroll")                                                     \
        for (int j = 0; j < 4; j++) {                                         \
            int idx2 = tid + 256 * j;                                         \
            int r = idx2 >> 3, c4 = idx2 & 7;                                 \
            rA[j] = *(const float4*)(Ab + (size_t)(m0 + r) * K + (k0) + c4 * 4); \
        }                                                                     \
        _Pragma("unroll")                                                     \
        for (int j = 0; j < 2; j++) {                                         \
            int idx2 = tid + 256 * j;                                         \
            int r = idx2 >> 4, c4 = idx2 & 15;                                \
            rB[j] = *(const float4*)(Yb + (size_t)((k0) + r) * N + n0 + c4 * 4); \
            rS[j] = rcb[(k0) + r];                                            \
        }                                                                     \
    }

#define P_STORE(s)                                                            \
    {                                                                         \
        uint32_t base = sb + (s) * PSTG;                                      \
        _Pragma("unroll")                                                     \
        for (int j = 0; j < 4; j++) {                                         \
            int idx2 = tid + 256 * j;                                         \
            int r = idx2 >> 3, c4 = idx2 & 7;                                 \
            uint32_t off = (uint32_t)(r * PA_STRIDE + c4 * 8);                \
            split_store(base + off, base + PA_TILE + off, rA[j]);             \
        }                                                                     \
        _Pragma("unroll")                                                     \
        for (int j = 0; j < 2; j++) {                                         \
            int idx2 = tid + 256 * j;                                         \
            int r = idx2 >> 4, c4 = idx2 & 15;                                \
            float4 v = rB[j];                                                 \
            v.x *= rS[j]; v.y *= rS[j]; v.z *= rS[j]; v.w *= rS[j];           \
            uint32_t off = (uint32_t)(r * PB_STRIDE + c4 * 8);                \
            split_store(base + 2 * PA_TILE + off, base + 2 * PA_TILE + PB_TILE + off, v); \
        }                                                                     \
    }

    const int nk = K / KC;
    P_LOAD(0);
    P_STORE(0);
    __syncthreads();

    for (int i = 0; i < nk; i++) {
        if (i + 1 < nk) P_LOAD((i + 1) * KC);
        {
            uint32_t base = sb + (i & 1) * PSTG;
            uint32_t bbase = base + 2 * PA_TILE;
#pragma unroll
            for (int kk = 0; kk < 2; kk++) {
                const int kb = kk * 16;
                uint32_t ahi[2][4], alo[2][4], bhi[4][2], blo[4][2];
#pragma unroll
                for (int mi = 0; mi < 2; mi++) {
                    int row = wm + mi * 16 + (lane & 15);
                    uint32_t addr = base + row * PA_STRIDE + (kb + ((lane >> 4) << 3)) * 2;
                    ldm_x4(ahi[mi], addr);
                    ldm_x4(alo[mi], addr + PA_TILE);
                }
#pragma unroll
                for (int ni = 0; ni < 4; ni++) {
                    int krow = kb + (lane & 7) + ((lane >> 3) & 1) * 8;
                    uint32_t addr = bbase + krow * PB_STRIDE + (wn + ni * 8) * 2;
                    ldm_x2_t(bhi[ni], addr);
                    ldm_x2_t(blo[ni], addr + PB_TILE);
                }
#pragma unroll
                for (int mi = 0; mi < 2; mi++)
#pragma unroll
                    for (int ni = 0; ni < 4; ni++)
                        mma_bf16(acc[mi][ni], ahi[mi], bhi[ni]);
#pragma unroll
                for (int mi = 0; mi < 2; mi++)
#pragma unroll
                    for (int ni = 0; ni < 4; ni++)
                        mma_bf16(acc[mi][ni], alo[mi], bhi[ni]);
#pragma unroll
                for (int mi = 0; mi < 2; mi++)
#pragma unroll
                    for (int ni = 0; ni < 4; ni++)
                        mma_bf16(acc[mi][ni], ahi[mi], blo[ni]);
            }
        }
        if (i + 1 < nk) P_STORE((i + 1) & 1);
        __syncthreads();
    }

#pragma unroll
    for (int mi = 0; mi < 2; mi++)
#pragma unroll
        for (int ni = 0; ni < 4; ni++) {
            int gm_base = m0 + wm + mi * 16 + (lane >> 2);
            int gn = n0 + wn + ni * 8 + (lane & 3) * 2;
            float bi0 = bias[gn], bi1 = bias[gn + 1];
#pragma unroll
            for (int h = 0; h < 2; h++) {
                int gm = gm_base + h * 8;
                float v0 = acc[mi][ni][h * 2 + 0] + bi0;
                float v1 = acc[mi][ni][h * 2 + 1] + bi1;
                if (relu) { v0 = fmaxf(v0, 0.f); v1 = fmaxf(v1, 0.f); }
                *(float2*)(Cb + (size_t)gm * N + gn) = make_float2(v0, v1);
            }
        }
}

// ---------------- transpose: Tt[b][e][v] = T[b][v][e] ------------------------
__global__ void transpose_kernel(const float* __restrict__ T, float* __restrict__ Tt) {
    __shared__ float tile[32][33];
    int b = blockIdx.z;
    const float* Tb = T + (size_t)b * NV * NE;
    float* Ob = Tt + (size_t)b * NV * NE;
    int e0 = blockIdx.x * 32, v0 = blockIdx.y * 32;
    int tx = threadIdx.x, ty = threadIdx.y;
#pragma unroll
    for (int j = 0; j < 32; j += 8)
        tile[ty + j][tx] = Tb[(size_t)(v0 + ty + j) * NE + e0 + tx];
    __syncthreads();
#pragma unroll
    for (int j = 0; j < 32; j += 8)
        Ob[(size_t)(e0 + ty + j) * NV + v0 + tx] = tile[tx][ty + j];
}

// ---------------- d = rows(X) . p  (warp per row) ----------------------------
__global__ void rowdot_kernel(const float* __restrict__ X, const float* __restrict__ p,
                              float* __restrict__ dout, int rows, int F) {
    int lane = threadIdx.x & 31;
    int wid  = threadIdx.x >> 5;
    int row  = blockIdx.x * 8 + wid;
    int b    = blockIdx.y;
    if (row >= rows) return;
    const float* xr = X + ((size_t)b * rows + row) * F;
    float s = 0.f;
    for (int f = lane; f < F; f += 32) s += xr[f] * p[f];
#pragma unroll
    for (int o = 16; o; o >>= 1) s += __shfl_xor_sync(0xffffffffu, s, o);
    if (lane == 0) dout[(size_t)b * rows + row] = s;
}

// ---------------- generic SIMT GEMM (small problems) -------------------------
__global__ void __launch_bounds__(256) gemm64_kernel(
    const float* __restrict__ A, const float* __restrict__ Bm, float* __restrict__ C,
    int M, int N, int K,
    long strideA, long strideB, long strideC,
    const float* __restrict__ rowScale, int strideRS,
    const float* __restrict__ bias, int reluOut, int reluA) {
    int b = blockIdx.z;
    const float* Ab = A + (size_t)b * strideA;
    const float* Bb = Bm + (size_t)b * strideB;
    float* Cb       = C + (size_t)b * strideC;
    const float* rs = rowScale ? rowScale + (size_t)b * strideRS : nullptr;
    int m0 = blockIdx.y * 64, n0 = blockIdx.x * 64;
    __shared__ float As[16][64];
    __shared__ float Bs[16][64];
    int tid = threadIdx.x;
    int tx = tid & 15, ty = tid >> 4;
    int arow = tid >> 2, ac4 = tid & 3;
    int bk = tid >> 4, bn4 = tid & 15;
    float acc[4][4] = {};
    for (int k0 = 0; k0 < K; k0 += 16) {
        float4 av = *(const float4*)(Ab + (size_t)(m0 + arow) * K + k0 + ac4 * 4);
        if (reluA) {
            av.x = fmaxf(av.x, 0.f); av.y = fmaxf(av.y, 0.f);
            av.z = fmaxf(av.z, 0.f); av.w = fmaxf(av.w, 0.f);
        }
        As[ac4 * 4 + 0][arow] = av.x; As[ac4 * 4 + 1][arow] = av.y;
        As[ac4 * 4 + 2][arow] = av.z; As[ac4 * 4 + 3][arow] = av.w;
        int col = n0 + bn4 * 4;
        float4 bv = make_float4(0.f, 0.f, 0.f, 0.f);
        if (col < N) bv = *(const float4*)(Bb + (size_t)(k0 + bk) * N + col);
        if (rs) { float s = rs[k0 + bk]; bv.x *= s; bv.y *= s; bv.z *= s; bv.w *= s; }
        *(float4*)&Bs[bk][bn4 * 4] = bv;
        __syncthreads();
#pragma unroll
        for (int k = 0; k < 16; k++) {
            float4 a  = *(const float4*)&As[k][ty * 4];
            float4 bq = *(const float4*)&Bs[k][tx * 4];
            acc[0][0] += a.x * bq.x; acc[0][1] += a.x * bq.y; acc[0][2] += a.x * bq.z; acc[0][3] += a.x * bq.w;
            acc[1][0] += a.y * bq.x; acc[1][1] += a.y * bq.y; acc[1][2] += a.y * bq.z; acc[1][3] += a.y * bq.w;
            acc[2][0] += a.z * bq.x; acc[2][1] += a.z * bq.y; acc[2][2] += a.z * bq.z; acc[2][3] += a.z * bq.w;
            acc[3][0] += a.w * bq.x; acc[3][1] += a.w * bq.y; acc[3][2] += a.w * bq.z; acc[3][3] += a.w * bq.w;
        }
        __syncthreads();
    }
#pragma unroll
    for (int i = 0; i < 4; i++) {
        int gm = m0 + ty * 4 + i;
#pragma unroll
        for (int j = 0; j < 4; j++) {
            int gn = n0 + tx * 4 + j;
            if (gn < N) {
                float v = acc[i][j];
                if (bias) v += bias[gn];
                if (reluOut) v = fmaxf(v, 0.f);
                Cb[(size_t)gm * N + gn] = v;
            }
        }
    }
}

__global__ void rcinv_kernel(const float* __restrict__ cm, float* __restrict__ rc, int n) {
    int i = blockIdx.x * blockDim.x + threadIdx.x;
    if (i < n) rc[i] = 1.0f / cm[i];
}

// ---------------- launch -----------------------------------------------------
extern "C" void kernel_launch(void* const* d_in, const int* in_sizes, int n_in,
                              void* d_out, int out_size) {
    const float* X     = (const float*)d_in[0];
    const float* Z     = (const float*)d_in[1];
    const float* adj_e = (const float*)d_in[2];
    const float* adj_v = (const float*)d_in[3];
    const float* Tm    = (const float*)d_in[4];
    const float* W1    = (const float*)d_in[5];
    const float* b1    = (const float*)d_in[6];
    const float* p1    = (const float*)d_in[7];
    const float* W2    = (const float*)d_in[8];
    const float* b2    = (const float*)d_in[9];
    const float* p2    = (const float*)d_in[10];
    const float* W3    = (const float*)d_in[11];
    const float* b3    = (const float*)d_in[12];
    const float* p3    = (const float*)d_in[13];
    float* out = (float*)d_out;

    int Bn = in_sizes[0] / (NV * FV);

    cudaFuncSetAttribute(mult_mma_kernel,
                         cudaFuncAttributeMaxDynamicSharedMemorySize, NSTAGE * STG);
    cudaFuncSetAttribute(prop_mma_kernel,
                         cudaFuncAttributeMaxDynamicSharedMemorySize, 2 * PSTG);
    const int MULT_SMEM = NSTAGE * STG;
    const int PROP_SMEM = 2 * PSTG;

    float *A, *Tt, *Y, *X1, *Z2, *dv, *rc, *cm;
    uint4 *SpT, *SpTt, *Dp;
    cudaGetSymbolAddress((void**)&A,   g_A);
    cudaGetSymbolAddress((void**)&Tt,  g_Tt);
    cudaGetSymbolAddress((void**)&SpT, g_SpT);
    cudaGetSymbolAddress((void**)&SpTt,g_SpTt);
    cudaGetSymbolAddress((void**)&Dp,  g_Dp);
    cudaGetSymbolAddress((void**)&Y,   g_Y);
    cudaGetSymbolAddress((void**)&X1,  g_X1);
    cudaGetSymbolAddress((void**)&Z2,  g_Z2);
    cudaGetSymbolAddress((void**)&dv,  g_d);
    cudaGetSymbolAddress((void**)&rc,  g_rc);
    cudaGetSymbolAddress((void**)&cm,  g_cm);

    const int NPAIR_V = (NV / 128) * (NV / 128 + 1) / 2;   // 36
    const int NPAIR_E = (NE / 128) * (NE / 128 + 1) / 2;   // 136
    const int PREP_BLKS = (NV * (NE / 8) + 255) / 256;     // same count for both shapes

    // transpose T once, then static splits of T and Tt
    transpose_kernel<<<dim3(NE / 32, NV / 32, Bn), dim3(32, 8)>>>(Tm, Tt);
    prep_split_kernel<<<dim3(PREP_BLKS, 1, Bn), 256>>>(Tm, nullptr, SpT, nullptr, NV, NE);
    prep_split_kernel<<<dim3(PREP_BLKS, 1, Bn), 256>>>(Tt, nullptr, SpTt, nullptr, NE, NV);

    // ===== Layer 1 (node): X1 = relu(norm(M1*adj_v) @ (X@W1) + b1) =====
    rowdot_kernel<<<dim3(NE / 8, Bn), 256>>>(Z, p1, dv, NE, FE);
    prep_split_kernel<<<dim3(PREP_BLKS, 1, Bn), 256>>>(Tm, dv, nullptr, Dp, NV, NE);
    gemm64_kernel<<<dim3(HH / 64, NV / 64, Bn), 256>>>(
        X, W1, Y, NV, HH, FV, (long)NV * FV, 0, (long)NV * HH, nullptr, 0, nullptr, 0, 0);
    cudaMemsetAsync(cm, 0, (size_t)Bn * NV * 4);
    mult_mma_kernel<<<dim3(NPAIR_V, 1, Bn), 512, MULT_SMEM>>>(SpT, Dp, adj_v, A, cm, NV, NE);
    rcinv_kernel<<<(Bn * NV + 255) / 256, 256>>>(cm, rc, Bn * NV);
    prop_mma_kernel<<<dim3(HH / 64, NV / 128, Bn), 256, PROP_SMEM>>>(
        A, Y, rc, b1, X1, NV, HH, NV, 1);

    // ===== Layer 2 (edge): Z2 = relu(norm(M2*adj_e) @ (relu(Z)@W2) + b2) =====
    rowdot_kernel<<<dim3(NV / 8, Bn), 256>>>(X1, p2, dv, NV, HH);
    prep_split_kernel<<<dim3(PREP_BLKS, 1, Bn), 256>>>(Tt, dv, nullptr, Dp, NE, NV);
    gemm64_kernel<<<dim3(1, NE / 64, Bn), 256>>>(
        Z, W2, Y, NE, FE, FE, (long)NE * FE, 0, (long)NE * FE, nullptr, 0, nullptr, 0, 1);
    cudaMemsetAsync(cm, 0, (size_t)Bn * NE * 4);
    mult_mma_kernel<<<dim3(NPAIR_E, 1, Bn), 512, MULT_SMEM>>>(SpTt, Dp, adj_e, A, cm, NE, NV);
    rcinv_kernel<<<(Bn * NE + 255) / 256, 256>>>(cm, rc, Bn * NE);
    prop_mma_kernel<<<dim3(FE / 64, NE / 128, Bn), 256, PROP_SMEM>>>(
        A, Y, rc, b2, Z2, NE, FE, NE, 1);

    // ===== Layer 3 (node): out = norm(M3*adj_v) @ (X1@W3) + b3 =====
    rowdot_kernel<<<dim3(NE / 8, Bn), 256>>>(Z2, p3, dv, NE, FE);
    prep_split_kernel<<<dim3(PREP_BLKS, 1, Bn), 256>>>(Tm, dv, nullptr, Dp, NV, NE);
    gemm64_kernel<<<dim3(1, NV / 64, Bn), 256>>>(
        X1, W3, Y, NV, CC, HH, (long)NV * HH, 0, (long)NV * CC, nullptr, 0, nullptr, 0, 0);
    cudaMemsetAsync(cm, 0, (size_t)Bn * NV * 4);
    mult_mma_kernel<<<dim3(NPAIR_V, 1, Bn), 512, MULT_SMEM>>>(SpT, Dp, adj_v, A, cm, NV, NE);
    rcinv_kernel<<<(Bn * NV + 255) / 256, 256>>>(cm, rc, Bn * NV);
    gemm64_kernel<<<dim3(1, NV / 64, Bn), 256>>>(
        A, Y, out, NV, CC, NV, (long)NV * NV, (long)NV * CC, (long)NV * CC, rc, NV, b3, 0, 0);
}